// round 16
// baseline (speedup 1.0000x reference)
#include <cuda_runtime.h>
#include <cstdint>

#define B 8
#define O 2048
#define Q 2048
#define D 128
#define KT 10      // expansion terms k = 0..9 (remainder <= 7.5e-7 rel at x<=1)
#define GS 12      // g_s row stride (floats), 16B-aligned
#define CPB 32     // CTAs per batch
#define CH 32      // obs rows per sub-chunk (2 sub-chunks per CTA)

// Scratch (allocation-free rule: device globals; zero-initialized at load).
// All accumulators/counters/flags are consumed AND reset within one kernel
// invocation, so every graph replay starts from the same (zero) state.
__device__ float g_M[B * KT * D];        // accumulated moments
__device__ float g_msum_in[B * KT];      // accumulated weight sums
__device__ unsigned int g_done[B];       // A-phase completion counters
__device__ unsigned int g_cdone[B];      // C-phase completion counters
__device__ volatile unsigned int g_ready[B];       // per-batch publish flags
__device__ __align__(16) float g_Mp[B * KT * D];   // projected moments
__device__ __align__(16) float g_msum[B * KT];     // weight-sum moments

__constant__ float c_invk[KT] = {0.f, 1.f, 1.f/2, 1.f/3, 1.f/4, 1.f/5, 1.f/6,
                                 1.f/7, 1.f/8, 1.f/9};

// ---------------------------------------------------------------------------
// Fused kernel: A-phase (moments) + last-CTA projection + C-phase (combine),
// pipelined per batch via release-acquire flags. 256 CTAs x 256 threads,
// __launch_bounds__(256,4) guarantees full residency (2/SM needed, 4 possible)
// so the intra-grid poll is deadlock-free.
// ---------------------------------------------------------------------------
__global__ __launch_bounds__(256, 4) void k_fused(
    const float* __restrict__ obs_emb,
    const float* __restrict__ obs_times,
    const float* __restrict__ obs_mask,
    const float* __restrict__ log_sigma,
    const float* __restrict__ W_proj,
    const float* __restrict__ query_times,
    const float* __restrict__ b_proj,
    float* __restrict__ out)
{
    __shared__ __align__(16) float g_s[CH * GS];   // 10 used, pad to 12
    __shared__ __align__(16) float red[KT * D];    // 5KB, reused as m_s
    __shared__ int s_last;

    const int tid = threadIdx.x;
    const int c   = blockIdx.x;          // 0..31
    const int b   = blockIdx.y;          // 0..7
    const float c2 = __expf(-2.0f * log_sigma[0]);   // 1/sigma^2

    // ================= A phase: two 32-obs sub-chunks =================
    const int e    = tid & 127;
    const int half = tid >> 7;
    float acc[KT];
#pragma unroll
    for (int k = 0; k < KT; ++k) acc[k] = 0.0f;
    float msacc = 0.0f;

#pragma unroll
    for (int sc = 0; sc < 2; ++sc) {
        const int o0 = (c * 2 + sc) * CH;
        __syncthreads();   // protect g_s from previous iteration's readers
        if (tid < CH) {
            const int o = o0 + tid;
            const float t  = obs_times[b * O + o];
            const float mk = obs_mask[b * O + o];
            const float xx = c2 * t;
            float g = mk * __expf(-0.5f * c2 * t * t);
            g_s[tid * GS + 0] = g;
#pragma unroll
            for (int k = 1; k < KT; ++k) {
                g *= xx * c_invk[k];
                g_s[tid * GS + k] = g;
            }
        }
        __syncthreads();

        if (tid < KT) {
            float s = 0.0f;
#pragma unroll
            for (int o = 0; o < CH; ++o) s += g_s[o * GS + tid];
            msacc += s;
        }

        const float* ebase = obs_emb + ((size_t)(b * O) + o0 + half * 16) * D + e;
        const float* gbase = g_s + half * 16 * GS;
#pragma unroll
        for (int oo = 0; oo < 16; ++oo) {
            const float xv = ebase[(size_t)oo * D];
            const float4 ga = *(const float4*)(gbase + oo * GS + 0);
            const float4 gb = *(const float4*)(gbase + oo * GS + 4);
            const float2 gc = *(const float2*)(gbase + oo * GS + 8);
            acc[0] = fmaf(ga.x, xv, acc[0]);   acc[1] = fmaf(ga.y, xv, acc[1]);
            acc[2] = fmaf(ga.z, xv, acc[2]);   acc[3] = fmaf(ga.w, xv, acc[3]);
            acc[4] = fmaf(gb.x, xv, acc[4]);   acc[5] = fmaf(gb.y, xv, acc[5]);
            acc[6] = fmaf(gb.z, xv, acc[6]);   acc[7] = fmaf(gb.w, xv, acc[7]);
            acc[8] = fmaf(gc.x, xv, acc[8]);   acc[9] = fmaf(gc.y, xv, acc[9]);
        }
    }
    if (tid < KT) atomicAdd(&g_msum_in[b * KT + tid], msacc);

    // combine the two halves via SMEM, then RED.ADD into g_M
    __syncthreads();   // g_s reads done; red is free
    if (half == 1) {
#pragma unroll
        for (int k = 0; k < KT; ++k) red[k * D + e] = acc[k];
    }
    __syncthreads();
    if (half == 0) {
        float* dst = g_M + (size_t)(b * KT) * D + e;
        const float* r0 = red + e;
#pragma unroll
        for (int k = 0; k < KT; ++k)
            atomicAdd(dst + k * D, acc[k] + r0[k * D]);
    }

    // ============ last-CTA-per-batch: projection + publish ============
    __threadfence();
    __syncthreads();   // red reads done before projector reuses it
    if (tid == 0)
        s_last = (atomicAdd(&g_done[b], 1u) == CPB - 1) ? 1 : 0;
    __syncthreads();

    if (s_last) {
        float* m_s = red;   // 1280 floats
        float* mb = g_M + (size_t)(b * KT) * D;
#pragma unroll
        for (int i = 0; i < 5; ++i) {
            const int idx = tid + i * 256;
            m_s[idx] = mb[idx];
            mb[idx] = 0.0f;                      // restore zero state
        }
        if (tid < KT) {
            g_msum[b * KT + tid] = g_msum_in[b * KT + tid];
            g_msum_in[b * KT + tid] = 0.0f;      // restore zero state
        }
        if (tid == 0) g_done[b] = 0;             // restore counter
        __syncthreads();

#pragma unroll
        for (int i = 0; i < 5; ++i) {
            const int idx = tid + i * 256;
            const int k  = idx >> 7;
            const int ep = idx & 127;
            const float4* wrow = (const float4*)(W_proj + (size_t)ep * D);
            const float4* mrow = (const float4*)(m_s + k * D);
            float dot = 0.0f;
#pragma unroll
            for (int j = 0; j < D / 4; ++j) {
                const float4 w4 = wrow[j];
                const float4 m4 = mrow[j];
                dot += w4.x * m4.x + w4.y * m4.y + w4.z * m4.z + w4.w * m4.w;
            }
            g_Mp[(size_t)(b * KT) * D + idx] = dot;
        }
        __threadfence();
        __syncthreads();
        if (tid == 0) g_ready[b] = 1;            // release
    }

    // ================= C phase: 64 q's for this CTA =================
    const int e4 = (tid & 31) * 4;
    const int qh = tid >> 5;             // 0..7, 8 q's each
    const int q0 = c * 64;

    if (tid == 0) {
        while (g_ready[b] == 0) __nanosleep(64);
        __threadfence();                 // acquire
    }
    __syncthreads();

    float4 mp[KT];
    float  ms[KT];
    const float* mpb = g_Mp + (size_t)b * KT * D + e4;
    const float* msb = g_msum + b * KT;
#pragma unroll
    for (int k = 0; k < KT; ++k) {
        mp[k] = *(const float4*)(mpb + k * D);
        ms[k] = msb[k];
    }
    const float4 bp = *(const float4*)&b_proj[e4];

#pragma unroll
    for (int p = 0; p < 2; ++p) {
        const float* qtp = query_times + b * Q + q0 + qh * 8 + p * 4;
        float qt[4], f[4];
#pragma unroll
        for (int j = 0; j < 4; ++j) qt[j] = qtp[j];
#pragma unroll
        for (int j = 0; j < 4; ++j) f[j] = __expf(-0.5f * c2 * qt[j] * qt[j]);

        float4 n[4];
        float  d[4];
#pragma unroll
        for (int j = 0; j < 4; ++j) {
            n[j].x = f[j] * mp[0].x; n[j].y = f[j] * mp[0].y;
            n[j].z = f[j] * mp[0].z; n[j].w = f[j] * mp[0].w;
            d[j] = f[j] * ms[0];
        }
#pragma unroll
        for (int k = 1; k < KT; ++k) {
#pragma unroll
            for (int j = 0; j < 4; ++j) {
                f[j] *= qt[j];
                n[j].x = fmaf(f[j], mp[k].x, n[j].x);
                n[j].y = fmaf(f[j], mp[k].y, n[j].y);
                n[j].z = fmaf(f[j], mp[k].z, n[j].z);
                n[j].w = fmaf(f[j], mp[k].w, n[j].w);
                d[j] = fmaf(f[j], ms[k], d[j]);
            }
        }
        float* ob = out + ((size_t)(b * Q) + q0 + qh * 8 + p * 4) * D + e4;
#pragma unroll
        for (int j = 0; j < 4; ++j) {
            const float inv = __fdividef(1.0f, fmaxf(d[j], 1e-8f));
            float4 v;
            v.x = fmaf(n[j].x, inv, bp.x);
            v.y = fmaf(n[j].y, inv, bp.y);
            v.z = fmaf(n[j].z, inv, bp.z);
            v.w = fmaf(n[j].w, inv, bp.w);
            *(float4*)(ob + (size_t)j * D) = v;
        }
    }

    // ---- C-phase completion: last finisher resets the batch flags ----
    __syncthreads();
    if (tid == 0) {
        if (atomicAdd(&g_cdone[b], 1u) == CPB - 1) {
            g_ready[b] = 0;          // restore for next replay
            g_cdone[b] = 0;
        }
    }
}

// ---------------------------------------------------------------------------
extern "C" void kernel_launch(void* const* d_in, const int* in_sizes, int n_in,
                              void* d_out, int out_size) {
    const float* obs_emb     = (const float*)d_in[0];
    const float* obs_times   = (const float*)d_in[1];
    const float* query_times = (const float*)d_in[2];
    const float* obs_mask    = (const float*)d_in[3];
    const float* log_sigma   = (const float*)d_in[4];
    const float* W_proj      = (const float*)d_in[5];
    const float* b_proj      = (const float*)d_in[6];
    float* out = (float*)d_out;

    dim3 grid(CPB, B);
    k_fused<<<grid, 256>>>(obs_emb, obs_times, obs_mask, log_sigma,
                           W_proj, query_times, b_proj, out);
}

// round 17
// speedup vs baseline: 2.4902x; 2.4902x over previous
#include <cuda_runtime.h>
#include <cstdint>

#define B 8
#define O 2048
#define Q 2048
#define D 128
#define KT 10      // expansion terms k = 0..9 (remainder <= 7.5e-7 rel at x<=1)
#define GS 12      // g_s row stride (floats), 16B-aligned
#define NCH 64     // obs chunks per batch
#define CH 32      // obs rows per chunk

// Scratch (allocation-free rule: device globals; zero-initialized at load).
// g_M / g_msum_in are atomic accumulators; kernel B consumes AND re-zeros
// them each call, so every kernel_launch invocation starts from zeros.
__device__ float g_M[B * KT * D];        // accumulated moments
__device__ float g_msum_in[B * KT];      // accumulated weight sums
__device__ __align__(16) float g_Mp[B * KT * D];   // projected moments
__device__ __align__(16) float g_msum[B * KT];     // weight-sum moments (for C)

__constant__ float c_invk[KT] = {0.f, 1.f, 1.f/2, 1.f/3, 1.f/4, 1.f/5, 1.f/6,
                                 1.f/7, 1.f/8, 1.f/9};

// PDL: wait for the upstream grid's memory to be visible (sm_90+ PTX).
__device__ __forceinline__ void grid_dep_wait() {
    asm volatile("griddepcontrol.wait;" ::: "memory");
}

// ---------------------------------------------------------------------------
// Kernel A (exact R13 shape — best measured):
// per (batch, 32-obs chunk) moments, reduced across CTAs via RED.
// 512 CTAs x 256 threads, e = tid&127, half = tid>>7 owns 16 rows.
// ---------------------------------------------------------------------------
__global__ __launch_bounds__(256) void k_moments(
    const float* __restrict__ obs_emb,
    const float* __restrict__ obs_times,
    const float* __restrict__ obs_mask,
    const float* __restrict__ log_sigma)
{
    __shared__ __align__(16) float g_s[CH * GS];   // 10 used, pad to 12
    __shared__ __align__(16) float red[KT * D];

    const int tid = threadIdx.x;
    const int c   = blockIdx.x;
    const int b   = blockIdx.y;
    const int o0  = c * CH;
    const float c2 = __expf(-2.0f * log_sigma[0]);   // 1/sigma^2

    // Phase 1: 32 threads compute g_k rows
    if (tid < CH) {
        const int o = o0 + tid;
        const float t  = obs_times[b * O + o];
        const float mk = obs_mask[b * O + o];
        const float xx = c2 * t;
        float g = mk * __expf(-0.5f * c2 * t * t);
        g_s[tid * GS + 0] = g;
#pragma unroll
        for (int k = 1; k < KT; ++k) {
            g *= xx * c_invk[k];
            g_s[tid * GS + k] = g;
        }
    }
    __syncthreads();

    // ms partials -> atomic accumulate
    if (tid < KT) {
        float s = 0.0f;
#pragma unroll
        for (int o = 0; o < CH; ++o) s += g_s[o * GS + tid];
        atomicAdd(&g_msum_in[b * KT + tid], s);
    }

    // Phase 2: accumulate moments over 16 rows per thread, loads in-loop.
    const int e    = tid & 127;
    const int half = tid >> 7;
    float acc[KT];
#pragma unroll
    for (int k = 0; k < KT; ++k) acc[k] = 0.0f;

    const float* ebase = obs_emb + ((size_t)(b * O) + o0 + half * 16) * D + e;
    const float* gbase = g_s + half * 16 * GS;
#pragma unroll
    for (int oo = 0; oo < 16; ++oo) {
        const float xv = ebase[(size_t)oo * D];
        const float4 ga = *(const float4*)(gbase + oo * GS + 0);
        const float4 gb = *(const float4*)(gbase + oo * GS + 4);
        const float2 gc = *(const float2*)(gbase + oo * GS + 8);
        acc[0] = fmaf(ga.x, xv, acc[0]);   acc[1] = fmaf(ga.y, xv, acc[1]);
        acc[2] = fmaf(ga.z, xv, acc[2]);   acc[3] = fmaf(ga.w, xv, acc[3]);
        acc[4] = fmaf(gb.x, xv, acc[4]);   acc[5] = fmaf(gb.y, xv, acc[5]);
        acc[6] = fmaf(gb.z, xv, acc[6]);   acc[7] = fmaf(gb.w, xv, acc[7]);
        acc[8] = fmaf(gc.x, xv, acc[8]);   acc[9] = fmaf(gc.y, xv, acc[9]);
    }

    // combine the two halves via SMEM, then RED.ADD into g_M
    if (half == 1) {
#pragma unroll
        for (int k = 0; k < KT; ++k) red[k * D + e] = acc[k];
    }
    __syncthreads();
    if (half == 0) {
        float* dst = g_M + (size_t)(b * KT) * D + e;
        const float* r0 = red + e;
#pragma unroll
        for (int k = 0; k < KT; ++k)
            atomicAdd(dst + k * D, acc[k] + r0[k * D]);
    }
}

// ---------------------------------------------------------------------------
// Kernel B (exact R13 shape): project accumulated moments through W;
// consume-and-rezero the atomic buffers. One CTA per (b, k), 128 threads.
// ---------------------------------------------------------------------------
__global__ __launch_bounds__(128) void k_project(
    const float* __restrict__ W_proj)
{
    __shared__ __align__(16) float m_s[D];
    const int e = threadIdx.x;
    const int k = blockIdx.x % KT;
    const int b = blockIdx.x / KT;

    grid_dep_wait();   // A's g_M / g_msum_in now visible

    float* mcell = g_M + (size_t)(b * KT + k) * D + e;
    m_s[e] = *mcell;
    *mcell = 0.0f;                       // restore zero state
    if (e == 0) {
        g_msum[b * KT + k] = g_msum_in[b * KT + k];
        g_msum_in[b * KT + k] = 0.0f;    // restore zero state
    }
    __syncthreads();

    // thread e = output dim: dot(W[e][:], m)
    const float4* wrow = (const float4*)(W_proj + (size_t)e * D);
    float dot = 0.0f;
#pragma unroll
    for (int i = 0; i < D / 4; ++i) {
        float4 w4 = wrow[i];
        const float4 m4 = *(const float4*)&m_s[i * 4];
        dot += w4.x * m4.x + w4.y * m4.y + w4.z * m4.z + w4.w * m4.w;
    }
    g_Mp[(size_t)(b * KT + k) * D + e] = dot;
}

// ---------------------------------------------------------------------------
// Kernel C v2: SMEM-staged Mp/msum (8x global dedup) + 8 q's per thread
// (two 4-q passes). out[q][e'] = (sum_k f_k Mp[k][e']) / (sum_k f_k msum[k]) + b[e']
// 256 CTAs (64 q each), 256 threads. PDL preamble before the wait.
// ---------------------------------------------------------------------------
__global__ __launch_bounds__(256) void k_combine(
    const float* __restrict__ query_times,
    const float* __restrict__ log_sigma,
    const float* __restrict__ b_proj,
    float* __restrict__ out)
{
    __shared__ __align__(16) float s_mp[KT * D];   // 5KB
    __shared__ float s_ms[KT];

    const int tid = threadIdx.x;
    const int b   = blockIdx.y;
    const int q0  = blockIdx.x * 64;
    const int e   = (tid & 31) * 4;
    const int qh  = tid >> 5;          // 0..7, 8 q's each

    // ---- preamble (independent of B's output) ----
    const float* qtb = query_times + b * Q + q0 + qh * 8;
    float qt[8];
#pragma unroll
    for (int j = 0; j < 8; ++j) qt[j] = qtb[j];
    const float c2 = __expf(-2.0f * log_sigma[0]);
    const float4 bp = *(const float4*)&b_proj[e];
    float fexp[8];
#pragma unroll
    for (int j = 0; j < 8; ++j) fexp[j] = __expf(-0.5f * c2 * qt[j] * qt[j]);

    grid_dep_wait();   // B's g_Mp / g_msum now visible

    // ---- cooperative SMEM stage: 5 coalesced loads/thread ----
    {
        const float* src = g_Mp + (size_t)b * KT * D;
#pragma unroll
        for (int i = 0; i < 5; ++i)
            s_mp[tid + i * 256] = src[tid + i * 256];
        if (tid < KT) s_ms[tid] = g_msum[b * KT + tid];
    }
    __syncthreads();

    // mp/ms registers from SMEM (broadcast-friendly)
    float4 mp[KT];
    float  ms[KT];
#pragma unroll
    for (int k = 0; k < KT; ++k) {
        mp[k] = *(const float4*)&s_mp[k * D + e];
        ms[k] = s_ms[k];
    }

#pragma unroll
    for (int p = 0; p < 2; ++p) {
        float f[4];
#pragma unroll
        for (int j = 0; j < 4; ++j) f[j] = fexp[p * 4 + j];

        float4 n[4];
        float  d[4];
#pragma unroll
        for (int j = 0; j < 4; ++j) {
            n[j].x = f[j] * mp[0].x; n[j].y = f[j] * mp[0].y;
            n[j].z = f[j] * mp[0].z; n[j].w = f[j] * mp[0].w;
            d[j] = f[j] * ms[0];
        }
#pragma unroll
        for (int k = 1; k < KT; ++k) {
#pragma unroll
            for (int j = 0; j < 4; ++j) {
                f[j] *= qt[p * 4 + j];
                n[j].x = fmaf(f[j], mp[k].x, n[j].x);
                n[j].y = fmaf(f[j], mp[k].y, n[j].y);
                n[j].z = fmaf(f[j], mp[k].z, n[j].z);
                n[j].w = fmaf(f[j], mp[k].w, n[j].w);
                d[j] = fmaf(f[j], ms[k], d[j]);
            }
        }
        float* ob = out + ((size_t)(b * Q) + q0 + qh * 8 + p * 4) * D + e;
#pragma unroll
        for (int j = 0; j < 4; ++j) {
            const float inv = __fdividef(1.0f, fmaxf(d[j], 1e-8f));
            float4 v;
            v.x = fmaf(n[j].x, inv, bp.x);
            v.y = fmaf(n[j].y, inv, bp.y);
            v.z = fmaf(n[j].z, inv, bp.z);
            v.w = fmaf(n[j].w, inv, bp.w);
            *(float4*)(ob + (size_t)j * D) = v;
        }
    }
}

// ---------------------------------------------------------------------------
extern "C" void kernel_launch(void* const* d_in, const int* in_sizes, int n_in,
                              void* d_out, int out_size) {
    const float* obs_emb     = (const float*)d_in[0];
    const float* obs_times   = (const float*)d_in[1];
    const float* query_times = (const float*)d_in[2];
    const float* obs_mask    = (const float*)d_in[3];
    const float* log_sigma   = (const float*)d_in[4];
    const float* W_proj      = (const float*)d_in[5];
    const float* b_proj      = (const float*)d_in[6];
    float* out = (float*)d_out;

    // A: normal launch
    dim3 gA(NCH, B);
    k_moments<<<gA, 256>>>(obs_emb, obs_times, obs_mask, log_sigma);

    // B, C: programmatic dependent launches (overlap ramp with predecessor drain)
    cudaLaunchAttribute attr[1];
    attr[0].id = cudaLaunchAttributeProgrammaticStreamSerialization;
    attr[0].val.programmaticStreamSerializationAllowed = 1;

    {
        cudaLaunchConfig_t cfg = {};
        cfg.gridDim  = dim3(B * KT);
        cfg.blockDim = dim3(128);
        cfg.stream   = 0;
        cfg.attrs    = attr;
        cfg.numAttrs = 1;
        cudaLaunchKernelEx(&cfg, k_project, W_proj);
    }
    {
        cudaLaunchConfig_t cfg = {};
        cfg.gridDim  = dim3(Q / 64, B);
        cfg.blockDim = dim3(256);
        cfg.stream   = 0;
        cfg.attrs    = attr;
        cfg.numAttrs = 1;
        cudaLaunchKernelEx(&cfg, k_combine, query_times, log_sigma, b_proj, out);
    }
}